// round 3
// baseline (speedup 1.0000x reference)
#include <cuda_runtime.h>
#include <math.h>

// Problem dims
#define BB 2048
#define TT 128
#define VV 25
#define HH 512
#define G4 2048   // 4*H
#define NC 100

// Tiling
#define BM 128
#define BJ 32          // j-columns per CTA; effective N tile = BJ*4 = 128 gate cols
#define BK 16
#define LDS_STRIDE 132 // 128 + 4 pad

// Persistent state (device globals: no allocation allowed)
__device__ float g_h[2][(size_t)BB * HH];   // ping-pong hidden state
__device__ float g_c[(size_t)BB * HH];      // cell state (in-place, CTA-private cells)

__device__ __forceinline__ unsigned long long ffma2(unsigned long long a,
                                                    unsigned long long b,
                                                    unsigned long long c) {
    unsigned long long d;
    asm("fma.rn.f32x2 %0, %1, %2, %3;" : "=l"(d) : "l"(a), "l"(b), "l"(c));
    return d;
}
__device__ __forceinline__ unsigned long long pack2(float x) {
    unsigned long long d;
    asm("mov.b64 %0, {%1, %1};" : "=l"(d) : "f"(x));
    return d;
}
__device__ __forceinline__ float2 unpack2(unsigned long long v) {
    float2 r;
    asm("mov.b64 {%0, %1}, %2;" : "=f"(r.x), "=f"(r.y) : "l"(v));
    return r;
}
__device__ __forceinline__ float sigmoidf_(float x) {
    return 1.0f / (1.0f + __expf(-x));
}

__global__ void init_state_kernel() {
    size_t i = (size_t)blockIdx.x * blockDim.x + threadIdx.x;
    size_t n = (size_t)BB * HH;
    if (i < n) {
        g_h[0][i] = 0.0f;
        g_c[i]    = 0.0f;
    }
}

// One LSTM timestep:
//   gates[b, g*H+j] = x[b,t,:]@W_ih[g*H+j,:] + h[b,:]@W_hh[g*H+j,:] + b_ih + b_hh
//   c = sig(f)*c + sig(i)*tanh(g);  h = sig(o)*tanh(c)
// CTA tile: BM rows x BJ hidden units (x 4 gates) = 128x128 accumulator tile.
// Column layout within tile: col = jl*4 + gate  (so all 4 gates of a unit sit in one thread).
__global__ __launch_bounds__(256, 2) void lstm_step_kernel(
    const float* __restrict__ msgs,
    const float* __restrict__ W_ih,
    const float* __restrict__ W_hh,
    const float* __restrict__ b_ih,
    const float* __restrict__ b_hh,
    int t)
{
    __shared__ __align__(16) float As[BK][LDS_STRIDE];
    __shared__ __align__(16) float Bs[BK][LDS_STRIDE];

    const float* h_in  = g_h[t & 1];
    float*       h_out = g_h[(t + 1) & 1];

    const int tid = threadIdx.x;
    const int tx  = tid & 15;   // 0..15 -> 2 hidden units each
    const int ty  = tid >> 4;   // 0..15 -> 8 rows each
    const int row0 = blockIdx.x * BM;
    const int j0   = blockIdx.y * BJ;

    unsigned long long acc2[8][4];
    #pragma unroll
    for (int i = 0; i < 8; i++)
        #pragma unroll
        for (int j = 0; j < 4; j++) acc2[i][j] = 0ULL;

    // Unified K: [0,512) from h_in/W_hh, [512,537) from msgs/W_ih, zero-pad to 544.
    for (int kc = 0; kc < 544; kc += BK) {
        // --- load A tile (activations): 128 rows x 16 k ---
        #pragma unroll
        for (int l = 0; l < 2; l++) {
            int p  = tid + l * 256;   // 0..511 float4 slots
            int r  = p >> 2;          // 0..127
            int kq = p & 3;           // 0..3
            int k  = kc + kq * 4;
            float4 v;
            if (k < HH) {
                v = *(const float4*)&h_in[(size_t)(row0 + r) * HH + k];
            } else {
                int kv = k - HH;
                const float* xp = &msgs[((size_t)(row0 + r) * TT + t) * VV];
                v.x = (kv + 0 < VV) ? xp[kv + 0] : 0.0f;
                v.y = (kv + 1 < VV) ? xp[kv + 1] : 0.0f;
                v.z = (kv + 2 < VV) ? xp[kv + 2] : 0.0f;
                v.w = (kv + 3 < VV) ? xp[kv + 3] : 0.0f;
            }
            As[kq * 4 + 0][r] = v.x;
            As[kq * 4 + 1][r] = v.y;
            As[kq * 4 + 2][r] = v.z;
            As[kq * 4 + 3][r] = v.w;
        }
        // --- load B tile (weights): 128 gate-cols x 16 k ---
        #pragma unroll
        for (int l = 0; l < 2; l++) {
            int p  = tid + l * 256;
            int c  = p >> 2;          // 0..127 tile column
            int kq = p & 3;
            int k  = kc + kq * 4;
            int jl = c >> 2;
            int g  = c & 3;
            int wrow = g * HH + j0 + jl;
            float4 v;
            if (k < HH) {
                v = *(const float4*)&W_hh[(size_t)wrow * HH + k];
            } else {
                int kv = k - HH;
                const float* wp = &W_ih[(size_t)wrow * VV];
                v.x = (kv + 0 < VV) ? wp[kv + 0] : 0.0f;
                v.y = (kv + 1 < VV) ? wp[kv + 1] : 0.0f;
                v.z = (kv + 2 < VV) ? wp[kv + 2] : 0.0f;
                v.w = (kv + 3 < VV) ? wp[kv + 3] : 0.0f;
            }
            Bs[kq * 4 + 0][c] = v.x;
            Bs[kq * 4 + 1][c] = v.y;
            Bs[kq * 4 + 2][c] = v.z;
            Bs[kq * 4 + 3][c] = v.w;
        }
        __syncthreads();

        #pragma unroll
        for (int k = 0; k < BK; k++) {
            float a[8];
            *(float4*)&a[0] = *(const float4*)&As[k][ty * 8];
            *(float4*)&a[4] = *(const float4*)&As[k][ty * 8 + 4];
            ulonglong2 t0 = *(const ulonglong2*)&Bs[k][tx * 8];
            ulonglong2 t1 = *(const ulonglong2*)&Bs[k][tx * 8 + 4];
            unsigned long long b2[4] = {t0.x, t0.y, t1.x, t1.y};
            #pragma unroll
            for (int i = 0; i < 8; i++) {
                unsigned long long a2 = pack2(a[i]);
                #pragma unroll
                for (int j = 0; j < 4; j++)
                    acc2[i][j] = ffma2(a2, b2[j], acc2[i][j]);
            }
        }
        __syncthreads();
    }

    // --- fused LSTM elementwise epilogue ---
    float bia[2][4];
    #pragma unroll
    for (int jj = 0; jj < 2; jj++) {
        int j = j0 + tx * 2 + jj;
        #pragma unroll
        for (int g = 0; g < 4; g++)
            bia[jj][g] = b_ih[g * HH + j] + b_hh[g * HH + j];
    }

    #pragma unroll
    for (int i = 0; i < 8; i++) {
        int row = row0 + ty * 8 + i;
        #pragma unroll
        for (int jj = 0; jj < 2; jj++) {
            float2 p01 = unpack2(acc2[i][jj * 2 + 0]);  // gates i, f
            float2 p23 = unpack2(acc2[i][jj * 2 + 1]);  // gates g, o
            float gi = sigmoidf_(p01.x + bia[jj][0]);
            float gf = sigmoidf_(p01.y + bia[jj][1]);
            float gg = tanhf(p23.x + bia[jj][2]);
            float go = sigmoidf_(p23.y + bia[jj][3]);
            size_t idx = (size_t)row * HH + (j0 + tx * 2 + jj);
            float cn = gf * g_c[idx] + gi * gg;
            g_c[idx] = cn;
            h_out[idx] = go * tanhf(cn);
        }
    }
}

// out[b, cls] = h_last[b,:] @ W_fc[cls,:] + b_fc[cls];  h_last lives in g_h[0] (T even)
__global__ void fc_kernel(const float* __restrict__ W_fc,
                          const float* __restrict__ b_fc,
                          float* __restrict__ out)
{
    __shared__ float hs[HH];
    int b = blockIdx.x;
    const float* hrow = g_h[0] + (size_t)b * HH;
    for (int k = threadIdx.x; k < HH; k += blockDim.x) hs[k] = hrow[k];
    __syncthreads();
    int cls = threadIdx.x;
    if (cls < NC) {
        const float* w = &W_fc[(size_t)cls * HH];
        float acc = 0.0f;
        #pragma unroll 8
        for (int k = 0; k < HH; k++) acc += hs[k] * w[k];
        out[(size_t)b * NC + cls] = acc + b_fc[cls];
    }
}

extern "C" void kernel_launch(void* const* d_in, const int* in_sizes, int n_in,
                              void* d_out, int out_size)
{
    const float* msgs = (const float*)d_in[0];
    const float* W_ih = (const float*)d_in[1];
    const float* W_hh = (const float*)d_in[2];
    const float* b_ih = (const float*)d_in[3];
    const float* b_hh = (const float*)d_in[4];
    const float* W_fc = (const float*)d_in[5];
    const float* b_fc = (const float*)d_in[6];
    float* out = (float*)d_out;

    init_state_kernel<<<(BB * HH + 255) / 256, 256>>>();

    dim3 grid(BB / BM, HH / BJ);  // 16 x 16
    for (int t = 0; t < TT; t++) {
        lstm_step_kernel<<<grid, 256>>>(msgs, W_ih, W_hh, b_ih, b_hh, t);
    }

    fc_kernel<<<BB, 128>>>(W_fc, b_fc, out);
}